// round 15
// baseline (speedup 1.0000x reference)
#include <cuda_runtime.h>
#include <cuda_fp16.h>
#include <cstdint>
#include <math.h>

#define N_NODES 20000
#define N_PAD   20096            // 314 * 64
#define NT64    314              // 64-row node tiles
#define N_EDGES 640000
#define HID 128
#define NB 3
#define NGS 47
#define NF 50
#define B_GRAPHS 16
#define LOG2F_ 0.69314718055994530942f
#define CUTF 10.0f
#define PI_F 3.14159265358979323846f
#define EDGE_TILES (N_EDGES / 128)   // 5000
#define PRE_BLOCKS ((N_EDGES + 255) / 256)   // 2500
#define INIT_BLOCKS 296

#define SA1 72     // halves stride for A tile (K=64 + 8 pad)
#define SA2 136    // halves stride for K=128 / N=128 tiles (+8 pad)

// ---- edge kernel smem byte offsets ----
#define OFF_W1h 0
#define OFF_W2h 18432
#define OFF_A   53248
#define OFF_H   71680                     // H tile / fp16 W staging
#define OFF_B1  106496
#define OFF_B2  107008
#define EK_SMEM 107520                    // 2 CTAs/SM

// ---- node kernel smem byte offsets (persistent, 1 CTA/SM) ----
#define NM_WA  0
#define NM_WB  34816
#define NM_WC  69632
#define NM_AT  104448                     // 64*136*2 = 17408
#define NM_HT  121856                     // 17408
#define NM_BA  139264
#define NM_BB  139776
#define NM_BO  140288
#define NM_O2  140544
#define NM_SMEM 140800

// ---------------- scratch ----------------
__device__ float g_h  [N_PAD * HID];
__device__ float g_xh [N_PAD * HID];
__device__ float g_agg[N_PAD * HID];
__device__ float g_Cc [N_EDGES];
__device__ half  g_feat[(size_t)N_EDGES * 64];

__device__ __forceinline__ float sspf(float x) {
    float e = __expf(-fabsf(x));
    return fmaxf(x, 0.f) + __logf(1.f + e) - LOG2F_;
}
__device__ __forceinline__ uint32_t smem_to_u32(const void* p) {
    uint32_t a;
    asm("{ .reg .u64 t; cvta.to.shared.u64 t, %1; cvt.u32.u64 %0, t; }" : "=r"(a) : "l"(p));
    return a;
}
__device__ __forceinline__ void ldm_x4(uint32_t& r0, uint32_t& r1, uint32_t& r2, uint32_t& r3, uint32_t a) {
    asm volatile("ldmatrix.sync.aligned.m8n8.x4.shared.b16 {%0,%1,%2,%3}, [%4];"
                 : "=r"(r0), "=r"(r1), "=r"(r2), "=r"(r3) : "r"(a));
}
__device__ __forceinline__ void ldm_x4t(uint32_t& r0, uint32_t& r1, uint32_t& r2, uint32_t& r3, uint32_t a) {
    asm volatile("ldmatrix.sync.aligned.m8n8.x4.trans.shared.b16 {%0,%1,%2,%3}, [%4];"
                 : "=r"(r0), "=r"(r1), "=r"(r2), "=r"(r3) : "r"(a));
}
__device__ __forceinline__ void mma16816(float* c, uint32_t a0, uint32_t a1, uint32_t a2, uint32_t a3,
                                         uint32_t b0, uint32_t b1) {
    asm volatile("mma.sync.aligned.m16n8k16.row.col.f32.f16.f16.f32 "
                 "{%0,%1,%2,%3}, {%4,%5,%6,%7}, {%8,%9}, {%0,%1,%2,%3};"
                 : "+f"(c[0]), "+f"(c[1]), "+f"(c[2]), "+f"(c[3])
                 : "r"(a0), "r"(a1), "r"(a2), "r"(a3), "r"(b0), "r"(b1));
}
__device__ __forceinline__ void cp_async16(uint32_t dst, const void* src) {
    asm volatile("cp.async.cg.shared.global [%0], [%1], 16;" :: "r"(dst), "l"(src) : "memory");
}
#define CP_COMMIT() asm volatile("cp.async.commit_group;" ::: "memory")
#define CP_WAIT0()  asm volatile("cp.async.wait_group 0;" ::: "memory")

__device__ __forceinline__ uint2 f4_to_h4(float4 v) {
    half2 h0 = __floats2half2_rn(v.x, v.y);
    half2 h1 = __floats2half2_rn(v.z, v.w);
    return make_uint2(*(uint32_t*)&h0, *(uint32_t*)&h1);
}

// ---------------- merged pre: edge features + node init (+ zero out) ----------------
__global__ void __launch_bounds__(256)
pre_kernel(const int* __restrict__ ei, const float* __restrict__ pos,
           const float* __restrict__ eattr, float* __restrict__ out,
           const int* __restrict__ z, const float* __restrict__ emb,
           const float* __restrict__ W) {
    if (blockIdx.x < PRE_BLOCKS) {
        // ---- edge feature precompute ----
        int e = blockIdx.x * blockDim.x + threadIdx.x;
        if (blockIdx.x == 0 && threadIdx.x < B_GRAPHS) out[threadIdx.x] = 0.f;
        if (e >= N_EDGES) return;
        int r = ei[e], c = ei[N_EDGES + e];
        float dx = pos[r * 3 + 0] - pos[c * 3 + 0];
        float dy = pos[r * 3 + 1] - pos[c * 3 + 1];
        float dz = pos[r * 3 + 2] - pos[c * 3 + 2];
        float ew = sqrtf(dx * dx + dy * dy + dz * dz);
        g_Cc[e] = 0.5f * (cosf(ew * (PI_F / CUTF)) + 1.f);

        const float step = CUTF / (float)(NGS - 1);
        float fv[64];
        fv[0] = eattr[e * NB + 0];
        fv[1] = eattr[e * NB + 1];
        fv[2] = eattr[e * NB + 2];
        float u  = ew / step;
        float gs = __expf(-0.5f * u * u);
        float m  = __expf(u - 0.5f);
        const float d = 0.36787944117144233f;   // e^-1
        fv[3] = gs;
        #pragma unroll
        for (int k = 1; k < NGS; k++) {
            gs *= m;
            m  *= d;
            fv[3 + k] = gs;
        }
        #pragma unroll
        for (int k = NF; k < 64; k++) fv[k] = 0.f;

        half2 tmp[32];
        #pragma unroll
        for (int j = 0; j < 32; j++) tmp[j] = __floats2half2_rn(fv[2 * j], fv[2 * j + 1]);
        uint4* dst = (uint4*)(g_feat + (size_t)e * 64);
        #pragma unroll
        for (int j = 0; j < 8; j++) dst[j] = ((uint4*)tmp)[j];
        return;
    }

    // ---- node init: h = emb[z]; xh = h @ cf1_0; agg = 0 ----
    extern __shared__ float sm[];
    float* Ws = sm;
    float* xs = Ws + HID * HID;
    for (int i = threadIdx.x; i < HID * HID; i += blockDim.x) Ws[i] = W[i];
    __syncthreads();

    const int bid = blockIdx.x - PRE_BLOCKS;
    const int wid = threadIdx.x >> 5, lane = threadIdx.x & 31;
    float* xw = xs + wid * 512;
    const int gw = bid * 8 + wid, nw = INIT_BLOCKS * 8;
    const int c0 = lane * 4;

    for (int gidx = gw; gidx < N_PAD / 4; gidx += nw) {
        int n0 = gidx * 4;
        #pragma unroll
        for (int j = 0; j < 4; j++) {
            int nn = n0 + j;
            float4 v = make_float4(0.f, 0.f, 0.f, 0.f);
            if (nn < N_NODES) {
                int zr = z[nn];
                v = ((const float4*)(emb + (size_t)zr * HID))[lane];
            }
            ((float4*)xw)[lane + 32 * j] = v;
            ((float4*)(g_h + (size_t)nn * HID))[lane] = v;
            ((float4*)(g_agg + (size_t)nn * HID))[lane] = make_float4(0.f, 0.f, 0.f, 0.f);
        }
        __syncwarp();
        float a[4][4];
        #pragma unroll
        for (int r = 0; r < 4; r++) { a[r][0] = a[r][1] = a[r][2] = a[r][3] = 0.f; }
        #pragma unroll 4
        for (int k = 0; k < HID; k++) {
            float4 w = *(const float4*)(Ws + k * HID + c0);
            #pragma unroll
            for (int r = 0; r < 4; r++) {
                float v = xw[r * HID + k];
                a[r][0] += v * w.x; a[r][1] += v * w.y; a[r][2] += v * w.z; a[r][3] += v * w.w;
            }
        }
        #pragma unroll
        for (int r = 0; r < 4; r++)
            *(float4*)(g_xh + (size_t)(n0 + r) * HID + c0) =
                make_float4(a[r][0], a[r][1], a[r][2], a[r][3]);
        __syncwarp();
    }
}

// ---------------- edge filter MLP (unchanged from R14) ----------------
__global__ void __launch_bounds__(256, 2)
edge_mma_kernel(const int* __restrict__ ei,
                const float* __restrict__ w1, const float* __restrict__ b1,
                const float* __restrict__ w2, const float* __restrict__ b2) {
    extern __shared__ char smem[];
    half* w1h = (half*)(smem + OFF_W1h);
    half* w2h = (half*)(smem + OFF_W2h);
    half* Ah  = (half*)(smem + OFF_A);
    half* Hh  = (half*)(smem + OFF_H);
    float* b1s = (float*)(smem + OFF_B1);
    float* b2s = (float*)(smem + OFF_B2);

    const int tid = threadIdx.x, wid = tid >> 5, lane = tid & 31;
    const int g = lane >> 2, tg = lane & 3;
    const int rt = wid & 3, nh = wid >> 2;
    const int aedge = tid >> 1, aseg = tid & 1;

    for (int i = tid * 4; i < 64 * 128; i += 1024) {
        int k = i >> 7, n = i & 127;
        float4 v = (k < NF) ? *(const float4*)(w1 + k * HID + n)
                            : make_float4(0.f, 0.f, 0.f, 0.f);
        *(uint2*)(w1h + k * SA2 + n) = f4_to_h4(v);
    }
    for (int i = tid * 4; i < 128 * 128; i += 1024) {
        int k = i >> 7, n = i & 127;
        *(uint2*)(w2h + k * SA2 + n) = f4_to_h4(*(const float4*)(w2 + k * HID + n));
    }
    if (tid < HID) { b1s[tid] = b1[tid]; b2s[tid] = b2[tid]; }

    const uint32_t aU  = smem_to_u32(Ah);
    const uint32_t hU  = smem_to_u32(Hh);
    const uint32_t w1U = smem_to_u32(w1h);
    const uint32_t w2U = smem_to_u32(w2h);
    const int lrow = lane & 15;
    const int lkh  = (lane >> 4) << 3;

    const uint32_t aCp = aU + (uint32_t)((aedge * SA1 + aseg * 32) << 1);
    {
        const half* src = g_feat + ((size_t)blockIdx.x * 128 + aedge) * 64 + aseg * 32;
        #pragma unroll
        for (int j = 0; j < 4; j++) cp_async16(aCp + j * 16, src + j * 8);
        CP_COMMIT();
    }
    CP_WAIT0();
    __syncthreads();

    for (int t = blockIdx.x; t < EDGE_TILES; t += gridDim.x) {
        const int e0 = t * 128;
        float acc[2][8][4];
        #pragma unroll
        for (int mt = 0; mt < 2; mt++)
            #pragma unroll
            for (int j = 0; j < 8; j++)
                #pragma unroll
                for (int q = 0; q < 4; q++) acc[mt][j][q] = 0.f;

        // ---- GEMM1 ----
        #pragma unroll
        for (int ks = 0; ks < 4; ks++) {
            const int k0 = ks * 16;
            uint32_t am[2][4];
            #pragma unroll
            for (int mt = 0; mt < 2; mt++) {
                uint32_t addr = aU + (uint32_t)(((rt * 32 + mt * 16 + lrow) * SA1 + k0 + lkh) << 1);
                ldm_x4(am[mt][0], am[mt][1], am[mt][2], am[mt][3], addr);
            }
            #pragma unroll
            for (int jj = 0; jj < 4; jj++) {
                uint32_t r0, r1, r2, r3;
                uint32_t addr = w1U + (uint32_t)(((k0 + lrow) * SA2 + nh * 64 + jj * 16 + lkh) << 1);
                ldm_x4t(r0, r1, r2, r3, addr);
                #pragma unroll
                for (int mt = 0; mt < 2; mt++) {
                    mma16816(acc[mt][2 * jj],     am[mt][0], am[mt][1], am[mt][2], am[mt][3], r0, r1);
                    mma16816(acc[mt][2 * jj + 1], am[mt][0], am[mt][1], am[mt][2], am[mt][3], r2, r3);
                }
            }
        }
        __syncthreads();

        const int tn = t + gridDim.x;
        if (tn < EDGE_TILES) {
            const half* src = g_feat + ((size_t)tn * 128 + aedge) * 64 + aseg * 32;
            #pragma unroll
            for (int j = 0; j < 4; j++) cp_async16(aCp + j * 16, src + j * 8);
        }
        CP_COMMIT();

        // ---- epilogue1: H = fp16(ssp(D1 + b1)) ----
        #pragma unroll
        for (int mt = 0; mt < 2; mt++) {
            int r0 = rt * 32 + mt * 16 + g;
            #pragma unroll
            for (int j = 0; j < 8; j++) {
                int c = nh * 64 + j * 8 + tg * 2;
                float bx = b1s[c], by = b1s[c + 1];
                *(half2*)(Hh + (size_t)r0 * SA2 + c) =
                    __floats2half2_rn(sspf(acc[mt][j][0] + bx), sspf(acc[mt][j][1] + by));
                *(half2*)(Hh + (size_t)(r0 + 8) * SA2 + c) =
                    __floats2half2_rn(sspf(acc[mt][j][2] + bx), sspf(acc[mt][j][3] + by));
            }
        }
        __syncthreads();

        // ---- GEMM2 ----
        #pragma unroll
        for (int mt = 0; mt < 2; mt++)
            #pragma unroll
            for (int j = 0; j < 8; j++)
                #pragma unroll
                for (int q = 0; q < 4; q++) acc[mt][j][q] = 0.f;
        #pragma unroll
        for (int ks = 0; ks < 8; ks++) {
            const int k0 = ks * 16;
            uint32_t am[2][4];
            #pragma unroll
            for (int mt = 0; mt < 2; mt++) {
                uint32_t addr = hU + (uint32_t)(((rt * 32 + mt * 16 + lrow) * SA2 + k0 + lkh) << 1);
                ldm_x4(am[mt][0], am[mt][1], am[mt][2], am[mt][3], addr);
            }
            #pragma unroll
            for (int jj = 0; jj < 4; jj++) {
                uint32_t r0, r1, r2, r3;
                uint32_t addr = w2U + (uint32_t)(((k0 + lrow) * SA2 + nh * 64 + jj * 16 + lkh) << 1);
                ldm_x4t(r0, r1, r2, r3, addr);
                #pragma unroll
                for (int mt = 0; mt < 2; mt++) {
                    mma16816(acc[mt][2 * jj],     am[mt][0], am[mt][1], am[mt][2], am[mt][3], r0, r1);
                    mma16816(acc[mt][2 * jj + 1], am[mt][0], am[mt][1], am[mt][2], am[mt][3], r2, r3);
                }
            }
        }
        __syncthreads();

        // ---- epilogue2: single-pass fp16 staging ----
        #pragma unroll
        for (int mt = 0; mt < 2; mt++) {
            int cr0 = mt * 64 + rt * 16 + g;
            #pragma unroll
            for (int j = 0; j < 8; j++) {
                int c = nh * 64 + j * 8 + tg * 2;
                float bx = b2s[c], by = b2s[c + 1];
                *(half2*)(Hh + (size_t)cr0 * SA2 + c) =
                    __floats2half2_rn(acc[mt][j][0] + bx, acc[mt][j][1] + by);
                *(half2*)(Hh + (size_t)(cr0 + 8) * SA2 + c) =
                    __floats2half2_rn(acc[mt][j][2] + bx, acc[mt][j][3] + by);
            }
        }
        __syncthreads();
        #pragma unroll
        for (int hb = 0; hb < 2; hb++) {
            int rowi[8], coli[8];
            float Ci[8];
            #pragma unroll
            for (int q = 0; q < 8; q++) {
                int cr = wid * 16 + hb * 8 + q;
                int mt = cr >> 6, cr64 = cr & 63;
                int er = (cr64 >> 4) * 32 + mt * 16 + (cr64 & 15);
                int e = e0 + er;
                rowi[q] = ei[e];
                coli[q] = ei[N_EDGES + e];
                Ci[q]   = g_Cc[e];
            }
            #pragma unroll
            for (int q = 0; q < 8; q++) {
                int cr = wid * 16 + hb * 8 + q;
                float4 xv = *(const float4*)(g_xh + (size_t)rowi[q] * HID + lane * 4);
                uint2 wraw = *(const uint2*)(Hh + (size_t)cr * SA2 + lane * 4);
                float2 f01 = __half22float2(*(half2*)&wraw.x);
                float2 f23 = __half22float2(*(half2*)&wraw.y);
                float C = Ci[q];
                float m0 = f01.x * C * xv.x;
                float m1 = f01.y * C * xv.y;
                float m2 = f23.x * C * xv.z;
                float m3 = f23.y * C * xv.w;
                asm volatile("red.global.add.v4.f32 [%0], {%1, %2, %3, %4};"
                             :: "l"(g_agg + (size_t)coli[q] * HID + lane * 4),
                                "f"(m0), "f"(m1), "f"(m2), "f"(m3) : "memory");
            }
        }
        CP_WAIT0();
        __syncthreads();
    }
}

// ---------------- node phase: M=64 tiles, 314 tiles, balanced ----------------
// 16 warps: rt = wid&3 (16-row tiles, 64 rows), nh = wid>>2 (32-col quarters)
template <int LAST>
__global__ void __launch_bounds__(512, 1)
node_mma(const float* __restrict__ wA, const float* __restrict__ bA,
         const float* __restrict__ wB, const float* __restrict__ bB,
         const float* __restrict__ wC,
         const float* __restrict__ o1b, const float* __restrict__ o2w,
         const float* __restrict__ o2b,
         const int* __restrict__ batch, float* __restrict__ out) {
    extern __shared__ char smem[];
    half* WAh = (half*)(smem + NM_WA);
    half* WBh = (half*)(smem + NM_WB);
    half* WCh = (half*)(smem + NM_WC);
    half* Ah  = (half*)(smem + NM_AT);   // 64 rows
    half* Hh  = (half*)(smem + NM_HT);   // 64 rows
    float* bAs = (float*)(smem + NM_BA);
    float* bBs = (float*)(smem + NM_BB);
    float* BOs = (float*)(smem + NM_BO);
    float* O2s = (float*)(smem + NM_O2);

    const int tid = threadIdx.x, wid = tid >> 5, lane = tid & 31;
    const int g = lane >> 2, tg = lane & 3;
    const int rt = wid & 3, nh = wid >> 2;

    for (int i = tid * 4; i < 128 * 128; i += 2048) {
        int k = i >> 7, n = i & 127;
        *(uint2*)(WAh + k * SA2 + n) = f4_to_h4(*(const float4*)(wA + k * HID + n));
        *(uint2*)(WBh + k * SA2 + n) = f4_to_h4(*(const float4*)(wB + k * HID + n));
    }
    if (LAST) {
        for (int i = tid * 4; i < 128 * 64; i += 2048) {
            int k = i >> 6, n = i & 63;
            *(uint2*)(WCh + k * SA2 + n) = f4_to_h4(*(const float4*)(wC + k * 64 + n));
        }
        if (tid < 64) { BOs[tid] = o1b[tid]; O2s[tid] = o2w[tid]; }
    } else {
        for (int i = tid * 4; i < 128 * 128; i += 2048) {
            int k = i >> 7, n = i & 127;
            *(uint2*)(WCh + k * SA2 + n) = f4_to_h4(*(const float4*)(wC + k * HID + n));
        }
    }
    if (tid < HID) { bAs[tid] = bA[tid]; bBs[tid] = bB[tid]; }

    const uint32_t aU  = smem_to_u32(Ah);
    const uint32_t hU  = smem_to_u32(Hh);
    const uint32_t wAU = smem_to_u32(WAh);
    const uint32_t wBU = smem_to_u32(WBh);
    const uint32_t wCU = smem_to_u32(WCh);
    const int lrow = lane & 15;
    const int lkh  = (lane >> 4) << 3;
    const float ob = LAST ? o2b[0] : 0.f;

    for (int t = blockIdx.x; t < NT64; t += gridDim.x) {
        const int n0 = t * 64;
        // batched agg tile load (64 rows), zero + convert
        {
            float4 pv[4];
            #pragma unroll
            for (int j = 0; j < 4; j++) {
                int i = tid + j * 512;
                pv[j] = ((const float4*)(g_agg + (size_t)(n0 + (i >> 5)) * HID))[i & 31];
            }
            #pragma unroll
            for (int j = 0; j < 4; j++) {
                int i = tid + j * 512;
                ((float4*)(g_agg + (size_t)(n0 + (i >> 5)) * HID))[i & 31] =
                    make_float4(0.f, 0.f, 0.f, 0.f);
                *(uint2*)(Ah + (size_t)(i >> 5) * SA2 + (i & 31) * 4) = f4_to_h4(pv[j]);
            }
        }
        __syncthreads();

        float acc[4][4];
        // ---- GEMM1: A @ WA  (warp: 16 rows x 32 cols) ----
        #pragma unroll
        for (int j = 0; j < 4; j++)
            #pragma unroll
            for (int q = 0; q < 4; q++) acc[j][q] = 0.f;
        #pragma unroll
        for (int ks = 0; ks < 8; ks++) {
            const int k0 = ks * 16;
            uint32_t am[4];
            uint32_t addr = aU + (uint32_t)(((rt * 16 + lrow) * SA2 + k0 + lkh) << 1);
            ldm_x4(am[0], am[1], am[2], am[3], addr);
            #pragma unroll
            for (int jj = 0; jj < 2; jj++) {
                uint32_t r0, r1, r2, r3;
                uint32_t baddr = wAU + (uint32_t)(((k0 + lrow) * SA2 + nh * 32 + jj * 16 + lkh) << 1);
                ldm_x4t(r0, r1, r2, r3, baddr);
                mma16816(acc[2 * jj],     am[0], am[1], am[2], am[3], r0, r1);
                mma16816(acc[2 * jj + 1], am[0], am[1], am[2], am[3], r2, r3);
            }
        }
        {
            int r0 = rt * 16 + g;
            #pragma unroll
            for (int j = 0; j < 4; j++) {
                int c = nh * 32 + j * 8 + tg * 2;
                float bx = bAs[c], by = bAs[c + 1];
                *(half2*)(Hh + (size_t)r0 * SA2 + c) =
                    __floats2half2_rn(sspf(acc[j][0] + bx), sspf(acc[j][1] + by));
                *(half2*)(Hh + (size_t)(r0 + 8) * SA2 + c) =
                    __floats2half2_rn(sspf(acc[j][2] + bx), sspf(acc[j][3] + by));
            }
        }
        __syncthreads();

        // ---- GEMM2: H @ WB ----
        #pragma unroll
        for (int j = 0; j < 4; j++)
            #pragma unroll
            for (int q = 0; q < 4; q++) acc[j][q] = 0.f;
        #pragma unroll
        for (int ks = 0; ks < 8; ks++) {
            const int k0 = ks * 16;
            uint32_t am[4];
            uint32_t addr = hU + (uint32_t)(((rt * 16 + lrow) * SA2 + k0 + lkh) << 1);
            ldm_x4(am[0], am[1], am[2], am[3], addr);
            #pragma unroll
            for (int jj = 0; jj < 2; jj++) {
                uint32_t r0, r1, r2, r3;
                uint32_t baddr = wBU + (uint32_t)(((k0 + lrow) * SA2 + nh * 32 + jj * 16 + lkh) << 1);
                ldm_x4t(r0, r1, r2, r3, baddr);
                mma16816(acc[2 * jj],     am[0], am[1], am[2], am[3], r0, r1);
                mma16816(acc[2 * jj + 1], am[0], am[1], am[2], am[3], r2, r3);
            }
        }
        {
            int r0 = rt * 16 + g;
            int gr0 = n0 + r0;
            #pragma unroll
            for (int j = 0; j < 4; j++) {
                int c = nh * 32 + j * 8 + tg * 2;
                float bx = bBs[c], by = bBs[c + 1];
                float2 h0 = *(const float2*)(g_h + (size_t)gr0 * HID + c);
                float2 h1 = *(const float2*)(g_h + (size_t)(gr0 + 8) * HID + c);
                float n00 = acc[j][0] + bx + h0.x;
                float n01 = acc[j][1] + by + h0.y;
                float n10 = acc[j][2] + bx + h1.x;
                float n11 = acc[j][3] + by + h1.y;
                if (!LAST) {
                    *(float2*)(g_h + (size_t)gr0 * HID + c)       = make_float2(n00, n01);
                    *(float2*)(g_h + (size_t)(gr0 + 8) * HID + c) = make_float2(n10, n11);
                }
                *(half2*)(Ah + (size_t)r0 * SA2 + c)       = __floats2half2_rn(n00, n01);
                *(half2*)(Ah + (size_t)(r0 + 8) * SA2 + c) = __floats2half2_rn(n10, n11);
            }
        }
        __syncthreads();

        // ---- GEMM3: A' @ WC ----
        const int NJ3 = LAST ? 1 : 2;
        #pragma unroll
        for (int j = 0; j < 4; j++)
            #pragma unroll
            for (int q = 0; q < 4; q++) acc[j][q] = 0.f;
        #pragma unroll
        for (int ks = 0; ks < 8; ks++) {
            const int k0 = ks * 16;
            uint32_t am[4];
            uint32_t addr = aU + (uint32_t)(((rt * 16 + lrow) * SA2 + k0 + lkh) << 1);
            ldm_x4(am[0], am[1], am[2], am[3], addr);
            #pragma unroll
            for (int jj = 0; jj < 2; jj++) {
                if (jj >= NJ3) break;
                uint32_t r0, r1, r2, r3;
                int ncol = LAST ? (nh * 16) : (nh * 32 + jj * 16);
                uint32_t baddr = wCU + (uint32_t)(((k0 + lrow) * SA2 + ncol + lkh) << 1);
                ldm_x4t(r0, r1, r2, r3, baddr);
                mma16816(acc[2 * jj],     am[0], am[1], am[2], am[3], r0, r1);
                mma16816(acc[2 * jj + 1], am[0], am[1], am[2], am[3], r2, r3);
            }
        }
        if (!LAST) {
            int gr0 = n0 + rt * 16 + g;
            #pragma unroll
            for (int j = 0; j < 4; j++) {
                int c = nh * 32 + j * 8 + tg * 2;
                *(float2*)(g_xh + (size_t)gr0 * HID + c) =
                    make_float2(acc[j][0], acc[j][1]);
                *(float2*)(g_xh + (size_t)(gr0 + 8) * HID + c) =
                    make_float2(acc[j][2], acc[j][3]);
            }
        } else {
            float s0 = 0.f, s1 = 0.f;
            #pragma unroll
            for (int j = 0; j < 2; j++) {
                int c = nh * 16 + j * 8 + tg * 2;
                float bx = BOs[c], by = BOs[c + 1];
                float wx = O2s[c], wy = O2s[c + 1];
                s0 += sspf(acc[j][0] + bx) * wx + sspf(acc[j][1] + by) * wy;
                s1 += sspf(acc[j][2] + bx) * wx + sspf(acc[j][3] + by) * wy;
            }
            s0 += __shfl_xor_sync(0xffffffffu, s0, 1);
            s0 += __shfl_xor_sync(0xffffffffu, s0, 2);
            s1 += __shfl_xor_sync(0xffffffffu, s1, 1);
            s1 += __shfl_xor_sync(0xffffffffu, s1, 2);
            if (tg == 0) {
                int rowA = n0 + rt * 16 + g;
                int rowB = rowA + 8;
                float add = (nh == 0) ? ob : 0.f;
                if (rowA < N_NODES) atomicAdd(&out[batch[rowA]], s0 + add);
                if (rowB < N_NODES) atomicAdd(&out[batch[rowB]], s1 + add);
            }
        }
        __syncthreads();
    }
}

// ---------------- launch ----------------
extern "C" void kernel_launch(void* const* d_in, const int* in_sizes, int n_in,
                              void* d_out, int out_size) {
    const int*   z      = (const int*)  d_in[0];
    const float* pos    = (const float*)d_in[1];
    const int*   batch  = (const int*)  d_in[2];
    const int*   ei     = (const int*)  d_in[3];
    const float* eattr  = (const float*)d_in[4];
    const float* emb    = (const float*)d_in[5];
    const float* mlp_w1 = (const float*)d_in[6];
    const float* mlp_b1 = (const float*)d_in[7];
    const float* mlp_w2 = (const float*)d_in[8];
    const float* mlp_b2 = (const float*)d_in[9];
    const float* cf1_w  = (const float*)d_in[10];
    const float* cf2_w  = (const float*)d_in[11];
    const float* cf2_b  = (const float*)d_in[12];
    const float* lin_w  = (const float*)d_in[13];
    const float* lin_b  = (const float*)d_in[14];
    const float* o1w    = (const float*)d_in[15];
    const float* o1b    = (const float*)d_in[16];
    const float* o2w    = (const float*)d_in[17];
    const float* o2b    = (const float*)d_in[18];
    float* out = (float*)d_out;

    const int PRE_SMEM = (HID * HID + 8 * 512) * (int)sizeof(float);
    cudaFuncSetAttribute(edge_mma_kernel, cudaFuncAttributeMaxDynamicSharedMemorySize, EK_SMEM);
    cudaFuncSetAttribute(pre_kernel,  cudaFuncAttributeMaxDynamicSharedMemorySize, PRE_SMEM);
    cudaFuncSetAttribute(node_mma<0>, cudaFuncAttributeMaxDynamicSharedMemorySize, NM_SMEM);
    cudaFuncSetAttribute(node_mma<1>, cudaFuncAttributeMaxDynamicSharedMemorySize, NM_SMEM);

    pre_kernel<<<PRE_BLOCKS + INIT_BLOCKS, 256, PRE_SMEM>>>(ei, pos, eattr, out, z, emb, cf1_w);

    for (int l = 0; l < 3; l++) {
        edge_mma_kernel<<<296, 256, EK_SMEM>>>(ei,
                                               mlp_w1 + (size_t)l * NF * HID, mlp_b1 + (size_t)l * HID,
                                               mlp_w2 + (size_t)l * HID * HID, mlp_b2 + (size_t)l * HID);
        if (l < 2) {
            node_mma<0><<<148, 512, NM_SMEM>>>(
                cf2_w + (size_t)l * HID * HID, cf2_b + (size_t)l * HID,
                lin_w + (size_t)l * HID * HID, lin_b + (size_t)l * HID,
                cf1_w + (size_t)(l + 1) * HID * HID,
                nullptr, nullptr, nullptr, batch, out);
        } else {
            node_mma<1><<<148, 512, NM_SMEM>>>(
                cf2_w + (size_t)l * HID * HID, cf2_b + (size_t)l * HID,
                lin_w + (size_t)l * HID * HID, lin_b + (size_t)l * HID,
                o1w, o1b, o2w, o2b, batch, out);
        }
    }
}

// round 16
// speedup vs baseline: 1.0889x; 1.0889x over previous
#include <cuda_runtime.h>
#include <cuda_fp16.h>
#include <cstdint>
#include <math.h>

#define N_NODES 20000
#define N_PAD   20096            // 157 * 128
#define NT_TILES 157
#define N_EDGES 640000
#define HID 128
#define NB 3
#define NGS 47
#define NF 50
#define B_GRAPHS 16
#define LOG2F_ 0.69314718055994530942f
#define CUTF 10.0f
#define PI_F 3.14159265358979323846f
#define EDGE_TILES (N_EDGES / 128)   // 5000

#define SA1 72     // halves stride for A tile (K=64 + 8 pad)
#define SA2 136    // halves stride for K=128 / N=128 tiles (+8 pad)

// ---- edge kernel smem byte offsets ----
#define OFF_W1h 0
#define OFF_W2h 18432
#define OFF_A   53248
#define OFF_H   71680                     // H tile / fp16 W staging (128 rows)
#define OFF_B1  106496
#define OFF_B2  107008
#define EK_SMEM 107520                    // 2 CTAs/SM

// ---- node kernel smem byte offsets (persistent, 1 CTA/SM) ----
#define NM_WA  0
#define NM_WB  34816
#define NM_WC  69632
#define NM_AT  104448
#define NM_HT  139264
#define NM_BA  174080
#define NM_BB  174592
#define NM_BO  175104
#define NM_O2  175360
#define NM_SMEM 175616

// ---------------- scratch ----------------
__device__ float g_h  [N_PAD * HID];
__device__ float g_xh [N_PAD * HID];
__device__ float g_agg[N_PAD * HID];
__device__ float g_Cc [N_EDGES];
__device__ half  g_feat[(size_t)N_EDGES * 64];

__device__ __forceinline__ float sspf(float x) {
    float e = __expf(-fabsf(x));
    return fmaxf(x, 0.f) + __logf(1.f + e) - LOG2F_;
}
__device__ __forceinline__ uint32_t smem_to_u32(const void* p) {
    uint32_t a;
    asm("{ .reg .u64 t; cvta.to.shared.u64 t, %1; cvt.u32.u64 %0, t; }" : "=r"(a) : "l"(p));
    return a;
}
__device__ __forceinline__ void ldm_x4(uint32_t& r0, uint32_t& r1, uint32_t& r2, uint32_t& r3, uint32_t a) {
    asm volatile("ldmatrix.sync.aligned.m8n8.x4.shared.b16 {%0,%1,%2,%3}, [%4];"
                 : "=r"(r0), "=r"(r1), "=r"(r2), "=r"(r3) : "r"(a));
}
__device__ __forceinline__ void ldm_x4t(uint32_t& r0, uint32_t& r1, uint32_t& r2, uint32_t& r3, uint32_t a) {
    asm volatile("ldmatrix.sync.aligned.m8n8.x4.trans.shared.b16 {%0,%1,%2,%3}, [%4];"
                 : "=r"(r0), "=r"(r1), "=r"(r2), "=r"(r3) : "r"(a));
}
__device__ __forceinline__ void mma16816(float* c, uint32_t a0, uint32_t a1, uint32_t a2, uint32_t a3,
                                         uint32_t b0, uint32_t b1) {
    asm volatile("mma.sync.aligned.m16n8k16.row.col.f32.f16.f16.f32 "
                 "{%0,%1,%2,%3}, {%4,%5,%6,%7}, {%8,%9}, {%0,%1,%2,%3};"
                 : "+f"(c[0]), "+f"(c[1]), "+f"(c[2]), "+f"(c[3])
                 : "r"(a0), "r"(a1), "r"(a2), "r"(a3), "r"(b0), "r"(b1));
}
__device__ __forceinline__ void cp_async16(uint32_t dst, const void* src) {
    asm volatile("cp.async.cg.shared.global [%0], [%1], 16;" :: "r"(dst), "l"(src) : "memory");
}
#define CP_COMMIT() asm volatile("cp.async.commit_group;" ::: "memory")
#define CP_WAIT0()  asm volatile("cp.async.wait_group 0;" ::: "memory")

__device__ __forceinline__ uint2 f4_to_h4(float4 v) {
    half2 h0 = __floats2half2_rn(v.x, v.y);
    half2 h1 = __floats2half2_rn(v.z, v.w);
    return make_uint2(*(uint32_t*)&h0, *(uint32_t*)&h1);
}

// ---------------- edge_pre (+ zero out) ----------------
__global__ void edge_pre_kernel(const int* __restrict__ ei, const float* __restrict__ pos,
                                const float* __restrict__ eattr, float* __restrict__ out) {
    int e = blockIdx.x * blockDim.x + threadIdx.x;
    if (blockIdx.x == 0 && threadIdx.x < B_GRAPHS) out[threadIdx.x] = 0.f;
    if (e >= N_EDGES) return;
    int r = ei[e], c = ei[N_EDGES + e];
    float dx = pos[r * 3 + 0] - pos[c * 3 + 0];
    float dy = pos[r * 3 + 1] - pos[c * 3 + 1];
    float dz = pos[r * 3 + 2] - pos[c * 3 + 2];
    float ew = sqrtf(dx * dx + dy * dy + dz * dz);
    g_Cc[e] = 0.5f * (cosf(ew * (PI_F / CUTF)) + 1.f);

    const float step = CUTF / (float)(NGS - 1);
    float fv[64];
    fv[0] = eattr[e * NB + 0];
    fv[1] = eattr[e * NB + 1];
    fv[2] = eattr[e * NB + 2];
    float u  = ew / step;
    float gs = __expf(-0.5f * u * u);
    float m  = __expf(u - 0.5f);
    const float d = 0.36787944117144233f;   // e^-1
    fv[3] = gs;
    #pragma unroll
    for (int k = 1; k < NGS; k++) {
        gs *= m;
        m  *= d;
        fv[3 + k] = gs;
    }
    #pragma unroll
    for (int k = NF; k < 64; k++) fv[k] = 0.f;

    half2 tmp[32];
    #pragma unroll
    for (int j = 0; j < 32; j++) tmp[j] = __floats2half2_rn(fv[2 * j], fv[2 * j + 1]);
    uint4* dst = (uint4*)(g_feat + (size_t)e * 64);
    #pragma unroll
    for (int j = 0; j < 8; j++) dst[j] = ((uint4*)tmp)[j];
}

// ---------------- node_init ----------------
__global__ void __launch_bounds__(256)
node_init(const int* __restrict__ z, const float* __restrict__ emb,
          const float* __restrict__ W) {
    extern __shared__ float sm[];
    float* Ws = sm;
    float* xs = Ws + HID * HID;
    for (int i = threadIdx.x; i < HID * HID; i += blockDim.x) Ws[i] = W[i];
    __syncthreads();

    const int wid = threadIdx.x >> 5, lane = threadIdx.x & 31;
    float* xw = xs + wid * 512;
    const int gw = blockIdx.x * 8 + wid, nw = gridDim.x * 8;
    const int c0 = lane * 4;

    for (int gidx = gw; gidx < N_PAD / 4; gidx += nw) {
        int n0 = gidx * 4;
        #pragma unroll
        for (int j = 0; j < 4; j++) {
            int nn = n0 + j;
            float4 v = make_float4(0.f, 0.f, 0.f, 0.f);
            if (nn < N_NODES) {
                int zr = z[nn];
                v = ((const float4*)(emb + (size_t)zr * HID))[lane];
            }
            ((float4*)xw)[lane + 32 * j] = v;
            ((float4*)(g_h + (size_t)nn * HID))[lane] = v;
            ((float4*)(g_agg + (size_t)nn * HID))[lane] = make_float4(0.f, 0.f, 0.f, 0.f);
        }
        __syncwarp();
        float a[4][4];
        #pragma unroll
        for (int r = 0; r < 4; r++) { a[r][0] = a[r][1] = a[r][2] = a[r][3] = 0.f; }
        #pragma unroll 4
        for (int k = 0; k < HID; k++) {
            float4 w = *(const float4*)(Ws + k * HID + c0);
            #pragma unroll
            for (int r = 0; r < 4; r++) {
                float v = xw[r * HID + k];
                a[r][0] += v * w.x; a[r][1] += v * w.y; a[r][2] += v * w.z; a[r][3] += v * w.w;
            }
        }
        #pragma unroll
        for (int r = 0; r < 4; r++)
            *(float4*)(g_xh + (size_t)(n0 + r) * HID + c0) =
                make_float4(a[r][0], a[r][1], a[r][2], a[r][3]);
        __syncwarp();
    }
}

// ---------------- edge filter MLP ----------------
__global__ void __launch_bounds__(256, 2)
edge_mma_kernel(const int* __restrict__ ei,
                const float* __restrict__ w1, const float* __restrict__ b1,
                const float* __restrict__ w2, const float* __restrict__ b2) {
    extern __shared__ char smem[];
    half* w1h = (half*)(smem + OFF_W1h);
    half* w2h = (half*)(smem + OFF_W2h);
    half* Ah  = (half*)(smem + OFF_A);
    half* Hh  = (half*)(smem + OFF_H);
    float* b1s = (float*)(smem + OFF_B1);
    float* b2s = (float*)(smem + OFF_B2);

    const int tid = threadIdx.x, wid = tid >> 5, lane = tid & 31;
    const int g = lane >> 2, tg = lane & 3;
    const int rt = wid & 3, nh = wid >> 2;
    const int aedge = tid >> 1, aseg = tid & 1;

    for (int i = tid * 4; i < 64 * 128; i += 1024) {
        int k = i >> 7, n = i & 127;
        float4 v = (k < NF) ? *(const float4*)(w1 + k * HID + n)
                            : make_float4(0.f, 0.f, 0.f, 0.f);
        *(uint2*)(w1h + k * SA2 + n) = f4_to_h4(v);
    }
    for (int i = tid * 4; i < 128 * 128; i += 1024) {
        int k = i >> 7, n = i & 127;
        *(uint2*)(w2h + k * SA2 + n) = f4_to_h4(*(const float4*)(w2 + k * HID + n));
    }
    if (tid < HID) { b1s[tid] = b1[tid]; b2s[tid] = b2[tid]; }

    const uint32_t aU  = smem_to_u32(Ah);
    const uint32_t hU  = smem_to_u32(Hh);
    const uint32_t w1U = smem_to_u32(w1h);
    const uint32_t w2U = smem_to_u32(w2h);
    const int lrow = lane & 15;
    const int lkh  = (lane >> 4) << 3;

    const uint32_t aCp = aU + (uint32_t)((aedge * SA1 + aseg * 32) << 1);
    {
        const half* src = g_feat + ((size_t)blockIdx.x * 128 + aedge) * 64 + aseg * 32;
        #pragma unroll
        for (int j = 0; j < 4; j++) cp_async16(aCp + j * 16, src + j * 8);
        CP_COMMIT();
    }
    CP_WAIT0();
    __syncthreads();   // weights + A(first) ready

    for (int t = blockIdx.x; t < EDGE_TILES; t += gridDim.x) {
        const int e0 = t * 128;
        float acc[2][8][4];
        #pragma unroll
        for (int mt = 0; mt < 2; mt++)
            #pragma unroll
            for (int j = 0; j < 8; j++)
                #pragma unroll
                for (int q = 0; q < 4; q++) acc[mt][j][q] = 0.f;

        // ---- GEMM1 ----
        #pragma unroll
        for (int ks = 0; ks < 4; ks++) {
            const int k0 = ks * 16;
            uint32_t am[2][4];
            #pragma unroll
            for (int mt = 0; mt < 2; mt++) {
                uint32_t addr = aU + (uint32_t)(((rt * 32 + mt * 16 + lrow) * SA1 + k0 + lkh) << 1);
                ldm_x4(am[mt][0], am[mt][1], am[mt][2], am[mt][3], addr);
            }
            #pragma unroll
            for (int jj = 0; jj < 4; jj++) {
                uint32_t r0, r1, r2, r3;
                uint32_t addr = w1U + (uint32_t)(((k0 + lrow) * SA2 + nh * 64 + jj * 16 + lkh) << 1);
                ldm_x4t(r0, r1, r2, r3, addr);
                #pragma unroll
                for (int mt = 0; mt < 2; mt++) {
                    mma16816(acc[mt][2 * jj],     am[mt][0], am[mt][1], am[mt][2], am[mt][3], r0, r1);
                    mma16816(acc[mt][2 * jj + 1], am[mt][0], am[mt][1], am[mt][2], am[mt][3], r2, r3);
                }
            }
        }
        __syncthreads();   // A consumed -> next cp.async may write

        const int tn = t + gridDim.x;
        if (tn < EDGE_TILES) {
            const half* src = g_feat + ((size_t)tn * 128 + aedge) * 64 + aseg * 32;
            #pragma unroll
            for (int j = 0; j < 4; j++) cp_async16(aCp + j * 16, src + j * 8);
        }
        CP_COMMIT();

        // ---- epilogue1: H = fp16(ssp(D1 + b1)) ----
        #pragma unroll
        for (int mt = 0; mt < 2; mt++) {
            int r0 = rt * 32 + mt * 16 + g;
            #pragma unroll
            for (int j = 0; j < 8; j++) {
                int c = nh * 64 + j * 8 + tg * 2;
                float bx = b1s[c], by = b1s[c + 1];
                *(half2*)(Hh + (size_t)r0 * SA2 + c) =
                    __floats2half2_rn(sspf(acc[mt][j][0] + bx), sspf(acc[mt][j][1] + by));
                *(half2*)(Hh + (size_t)(r0 + 8) * SA2 + c) =
                    __floats2half2_rn(sspf(acc[mt][j][2] + bx), sspf(acc[mt][j][3] + by));
            }
        }
        __syncthreads();   // H ready

        // ---- GEMM2 ----
        #pragma unroll
        for (int mt = 0; mt < 2; mt++)
            #pragma unroll
            for (int j = 0; j < 8; j++)
                #pragma unroll
                for (int q = 0; q < 4; q++) acc[mt][j][q] = 0.f;
        #pragma unroll
        for (int ks = 0; ks < 8; ks++) {
            const int k0 = ks * 16;
            uint32_t am[2][4];
            #pragma unroll
            for (int mt = 0; mt < 2; mt++) {
                uint32_t addr = hU + (uint32_t)(((rt * 32 + mt * 16 + lrow) * SA2 + k0 + lkh) << 1);
                ldm_x4(am[mt][0], am[mt][1], am[mt][2], am[mt][3], addr);
            }
            #pragma unroll
            for (int jj = 0; jj < 4; jj++) {
                uint32_t r0, r1, r2, r3;
                uint32_t addr = w2U + (uint32_t)(((k0 + lrow) * SA2 + nh * 64 + jj * 16 + lkh) << 1);
                ldm_x4t(r0, r1, r2, r3, addr);
                #pragma unroll
                for (int mt = 0; mt < 2; mt++) {
                    mma16816(acc[mt][2 * jj],     am[mt][0], am[mt][1], am[mt][2], am[mt][3], r0, r1);
                    mma16816(acc[mt][2 * jj + 1], am[mt][0], am[mt][1], am[mt][2], am[mt][3], r2, r3);
                }
            }
        }
        __syncthreads();   // Hh free -> fp16 W staging may overwrite

        // ---- epilogue2: single-pass fp16 staging; meta loads overlap staging ----
        // batch-0 meta issued BEFORE staging stores + sync (latency hides under barrier)
        int rowi[8], coli[8];
        float Ci[8];
        #pragma unroll
        for (int q = 0; q < 8; q++) {
            int cr = wid * 16 + q;
            int mt = cr >> 6, cr64 = cr & 63;
            int er = (cr64 >> 4) * 32 + mt * 16 + (cr64 & 15);
            int e = e0 + er;
            rowi[q] = ei[e];
            coli[q] = ei[N_EDGES + e];
            Ci[q]   = g_Cc[e];
        }
        #pragma unroll
        for (int mt = 0; mt < 2; mt++) {
            int cr0 = mt * 64 + rt * 16 + g;
            #pragma unroll
            for (int j = 0; j < 8; j++) {
                int c = nh * 64 + j * 8 + tg * 2;
                float bx = b2s[c], by = b2s[c + 1];
                *(half2*)(Hh + (size_t)cr0 * SA2 + c) =
                    __floats2half2_rn(acc[mt][j][0] + bx, acc[mt][j][1] + by);
                *(half2*)(Hh + (size_t)(cr0 + 8) * SA2 + c) =
                    __floats2half2_rn(acc[mt][j][2] + bx, acc[mt][j][3] + by);
            }
        }
        __syncthreads();
        #pragma unroll
        for (int hb = 0; hb < 2; hb++) {
            #pragma unroll
            for (int q = 0; q < 8; q++) {
                int cr = wid * 16 + hb * 8 + q;
                float4 xv = *(const float4*)(g_xh + (size_t)rowi[q] * HID + lane * 4);
                uint2 wraw = *(const uint2*)(Hh + (size_t)cr * SA2 + lane * 4);
                float2 f01 = __half22float2(*(half2*)&wraw.x);
                float2 f23 = __half22float2(*(half2*)&wraw.y);
                float C = Ci[q];
                float m0 = f01.x * C * xv.x;
                float m1 = f01.y * C * xv.y;
                float m2 = f23.x * C * xv.z;
                float m3 = f23.y * C * xv.w;
                asm volatile("red.global.add.v4.f32 [%0], {%1, %2, %3, %4};"
                             :: "l"(g_agg + (size_t)coli[q] * HID + lane * 4),
                                "f"(m0), "f"(m1), "f"(m2), "f"(m3) : "memory");
            }
            // load batch-1 meta during batch-0 scatter
            if (hb == 0) {
                #pragma unroll
                for (int q = 0; q < 8; q++) {
                    int cr = wid * 16 + 8 + q;
                    int mt = cr >> 6, cr64 = cr & 63;
                    int er = (cr64 >> 4) * 32 + mt * 16 + (cr64 & 15);
                    int e = e0 + er;
                    rowi[q] = ei[e];
                    coli[q] = ei[N_EDGES + e];
                    Ci[q]   = g_Cc[e];
                }
            }
        }
        CP_WAIT0();
        __syncthreads();   // staging free + A(t+1) visible to all
    }
}

// ---------------- node phase (persistent, 512 threads, M=128 tiles) ----------------
// warp layout: rt = wid&7 (16-row tiles), nh = wid>>3 (64-col halves)
template <int LAST>
__global__ void __launch_bounds__(512, 1)
node_mma(const float* __restrict__ wA, const float* __restrict__ bA,
         const float* __restrict__ wB, const float* __restrict__ bB,
         const float* __restrict__ wC,
         const float* __restrict__ o1b, const float* __restrict__ o2w,
         const float* __restrict__ o2b,
         const int* __restrict__ batch, float* __restrict__ out) {
    extern __shared__ char smem[];
    half* WAh = (half*)(smem + NM_WA);
    half* WBh = (half*)(smem + NM_WB);
    half* WCh = (half*)(smem + NM_WC);
    half* Ah  = (half*)(smem + NM_AT);
    half* Hh  = (half*)(smem + NM_HT);
    float* bAs = (float*)(smem + NM_BA);
    float* bBs = (float*)(smem + NM_BB);
    float* BOs = (float*)(smem + NM_BO);
    float* O2s = (float*)(smem + NM_O2);

    const int tid = threadIdx.x, wid = tid >> 5, lane = tid & 31;
    const int g = lane >> 2, tg = lane & 3;
    const int rt = wid & 7, nh = wid >> 3;

    for (int i = tid * 4; i < 128 * 128; i += 2048) {
        int k = i >> 7, n = i & 127;
        *(uint2*)(WAh + k * SA2 + n) = f4_to_h4(*(const float4*)(wA + k * HID + n));
        *(uint2*)(WBh + k * SA2 + n) = f4_to_h4(*(const float4*)(wB + k * HID + n));
    }
    if (LAST) {
        for (int i = tid * 4; i < 128 * 64; i += 2048) {
            int k = i >> 6, n = i & 63;
            *(uint2*)(WCh + k * SA2 + n) = f4_to_h4(*(const float4*)(wC + k * 64 + n));
        }
        if (tid < 64) { BOs[tid] = o1b[tid]; O2s[tid] = o2w[tid]; }
    } else {
        for (int i = tid * 4; i < 128 * 128; i += 2048) {
            int k = i >> 7, n = i & 127;
            *(uint2*)(WCh + k * SA2 + n) = f4_to_h4(*(const float4*)(wC + k * HID + n));
        }
    }
    if (tid < HID) { bAs[tid] = bA[tid]; bBs[tid] = bB[tid]; }

    const uint32_t aU  = smem_to_u32(Ah);
    const uint32_t hU  = smem_to_u32(Hh);
    const uint32_t wAU = smem_to_u32(WAh);
    const uint32_t wBU = smem_to_u32(WBh);
    const uint32_t wCU = smem_to_u32(WCh);
    const int lrow = lane & 15;
    const int lkh  = (lane >> 4) << 3;
    const float ob = LAST ? o2b[0] : 0.f;

    for (int t = blockIdx.x; t < NT_TILES; t += gridDim.x) {
        const int n0 = t * 128;
        {
            float4 pv[8];
            #pragma unroll
            for (int j = 0; j < 8; j++) {
                int i = tid + j * 512;
                pv[j] = ((const float4*)(g_agg + (size_t)(n0 + (i >> 5)) * HID))[i & 31];
            }
            #pragma unroll
            for (int j = 0; j < 8; j++) {
                int i = tid + j * 512;
                ((float4*)(g_agg + (size_t)(n0 + (i >> 5)) * HID))[i & 31] =
                    make_float4(0.f, 0.f, 0.f, 0.f);
                *(uint2*)(Ah + (size_t)(i >> 5) * SA2 + (i & 31) * 4) = f4_to_h4(pv[j]);
            }
        }
        __syncthreads();

        float acc[8][4];
        // ---- GEMM1: A @ WA ----
        #pragma unroll
        for (int j = 0; j < 8; j++)
            #pragma unroll
            for (int q = 0; q < 4; q++) acc[j][q] = 0.f;
        #pragma unroll
        for (int ks = 0; ks < 8; ks++) {
            const int k0 = ks * 16;
            uint32_t am[4];
            uint32_t addr = aU + (uint32_t)(((rt * 16 + lrow) * SA2 + k0 + lkh) << 1);
            ldm_x4(am[0], am[1], am[2], am[3], addr);
            #pragma unroll
            for (int jj = 0; jj < 4; jj++) {
                uint32_t r0, r1, r2, r3;
                uint32_t baddr = wAU + (uint32_t)(((k0 + lrow) * SA2 + nh * 64 + jj * 16 + lkh) << 1);
                ldm_x4t(r0, r1, r2, r3, baddr);
                mma16816(acc[2 * jj],     am[0], am[1], am[2], am[3], r0, r1);
                mma16816(acc[2 * jj + 1], am[0], am[1], am[2], am[3], r2, r3);
            }
        }
        {
            int r0 = rt * 16 + g;
            #pragma unroll
            for (int j = 0; j < 8; j++) {
                int c = nh * 64 + j * 8 + tg * 2;
                float bx = bAs[c], by = bAs[c + 1];
                *(half2*)(Hh + (size_t)r0 * SA2 + c) =
                    __floats2half2_rn(sspf(acc[j][0] + bx), sspf(acc[j][1] + by));
                *(half2*)(Hh + (size_t)(r0 + 8) * SA2 + c) =
                    __floats2half2_rn(sspf(acc[j][2] + bx), sspf(acc[j][3] + by));
            }
        }
        __syncthreads();

        // ---- GEMM2: H @ WB ----
        #pragma unroll
        for (int j = 0; j < 8; j++)
            #pragma unroll
            for (int q = 0; q < 4; q++) acc[j][q] = 0.f;
        #pragma unroll
        for (int ks = 0; ks < 8; ks++) {
            const int k0 = ks * 16;
            uint32_t am[4];
            uint32_t addr = hU + (uint32_t)(((rt * 16 + lrow) * SA2 + k0 + lkh) << 1);
            ldm_x4(am[0], am[1], am[2], am[3], addr);
            #pragma unroll
            for (int jj = 0; jj < 4; jj++) {
                uint32_t r0, r1, r2, r3;
                uint32_t baddr = wBU + (uint32_t)(((k0 + lrow) * SA2 + nh * 64 + jj * 16 + lkh) << 1);
                ldm_x4t(r0, r1, r2, r3, baddr);
                mma16816(acc[2 * jj],     am[0], am[1], am[2], am[3], r0, r1);
                mma16816(acc[2 * jj + 1], am[0], am[1], am[2], am[3], r2, r3);
            }
        }
        {
            int r0 = rt * 16 + g;
            int gr0 = n0 + r0;
            #pragma unroll
            for (int j = 0; j < 8; j++) {
                int c = nh * 64 + j * 8 + tg * 2;
                float bx = bBs[c], by = bBs[c + 1];
                float2 h0 = *(const float2*)(g_h + (size_t)gr0 * HID + c);
                float2 h1 = *(const float2*)(g_h + (size_t)(gr0 + 8) * HID + c);
                float n00 = acc[j][0] + bx + h0.x;
                float n01 = acc[j][1] + by + h0.y;
                float n10 = acc[j][2] + bx + h1.x;
                float n11 = acc[j][3] + by + h1.y;
                if (!LAST) {
                    *(float2*)(g_h + (size_t)gr0 * HID + c)       = make_float2(n00, n01);
                    *(float2*)(g_h + (size_t)(gr0 + 8) * HID + c) = make_float2(n10, n11);
                }
                *(half2*)(Ah + (size_t)r0 * SA2 + c)       = __floats2half2_rn(n00, n01);
                *(half2*)(Ah + (size_t)(r0 + 8) * SA2 + c) = __floats2half2_rn(n10, n11);
            }
        }
        __syncthreads();

        // ---- GEMM3: A' @ WC ----
        const int NJ3 = LAST ? 2 : 4;
        #pragma unroll
        for (int j = 0; j < 8; j++)
            #pragma unroll
            for (int q = 0; q < 4; q++) acc[j][q] = 0.f;
        #pragma unroll
        for (int ks = 0; ks < 8; ks++) {
            const int k0 = ks * 16;
            uint32_t am[4];
            uint32_t addr = aU + (uint32_t)(((rt * 16 + lrow) * SA2 + k0 + lkh) << 1);
            ldm_x4(am[0], am[1], am[2], am[3], addr);
            #pragma unroll
            for (int jj = 0; jj < 4; jj++) {
                if (jj >= NJ3) break;
                uint32_t r0, r1, r2, r3;
                int ncol = LAST ? (nh * 32 + jj * 16) : (nh * 64 + jj * 16);
                uint32_t baddr = wCU + (uint32_t)(((k0 + lrow) * SA2 + ncol + lkh) << 1);
                ldm_x4t(r0, r1, r2, r3, baddr);
                mma16816(acc[2 * jj],     am[0], am[1], am[2], am[3], r0, r1);
                mma16816(acc[2 * jj + 1], am[0], am[1], am[2], am[3], r2, r3);
            }
        }
        if (!LAST) {
            int gr0 = n0 + rt * 16 + g;
            #pragma unroll
            for (int j = 0; j < 8; j++) {
                int c = nh * 64 + j * 8 + tg * 2;
                *(float2*)(g_xh + (size_t)gr0 * HID + c) =
                    make_float2(acc[j][0], acc[j][1]);
                *(float2*)(g_xh + (size_t)(gr0 + 8) * HID + c) =
                    make_float2(acc[j][2], acc[j][3]);
            }
        } else {
            float s0 = 0.f, s1 = 0.f;
            #pragma unroll
            for (int j = 0; j < 4; j++) {
                int c = nh * 32 + j * 8 + tg * 2;
                float bx = BOs[c], by = BOs[c + 1];
                float wx = O2s[c], wy = O2s[c + 1];
                s0 += sspf(acc[j][0] + bx) * wx + sspf(acc[j][1] + by) * wy;
                s1 += sspf(acc[j][2] + bx) * wx + sspf(acc[j][3] + by) * wy;
            }
            s0 += __shfl_xor_sync(0xffffffffu, s0, 1);
            s0 += __shfl_xor_sync(0xffffffffu, s0, 2);
            s1 += __shfl_xor_sync(0xffffffffu, s1, 1);
            s1 += __shfl_xor_sync(0xffffffffu, s1, 2);
            if (tg == 0) {
                int rowA = n0 + rt * 16 + g;
                int rowB = rowA + 8;
                float add = (nh == 0) ? ob : 0.f;
                if (rowA < N_NODES) atomicAdd(&out[batch[rowA]], s0 + add);
                if (rowB < N_NODES) atomicAdd(&out[batch[rowB]], s1 + add);
            }
        }
        __syncthreads();
    }
}

// ---------------- launch ----------------
extern "C" void kernel_launch(void* const* d_in, const int* in_sizes, int n_in,
                              void* d_out, int out_size) {
    const int*   z      = (const int*)  d_in[0];
    const float* pos    = (const float*)d_in[1];
    const int*   batch  = (const int*)  d_in[2];
    const int*   ei     = (const int*)  d_in[3];
    const float* eattr  = (const float*)d_in[4];
    const float* emb    = (const float*)d_in[5];
    const float* mlp_w1 = (const float*)d_in[6];
    const float* mlp_b1 = (const float*)d_in[7];
    const float* mlp_w2 = (const float*)d_in[8];
    const float* mlp_b2 = (const float*)d_in[9];
    const float* cf1_w  = (const float*)d_in[10];
    const float* cf2_w  = (const float*)d_in[11];
    const float* cf2_b  = (const float*)d_in[12];
    const float* lin_w  = (const float*)d_in[13];
    const float* lin_b  = (const float*)d_in[14];
    const float* o1w    = (const float*)d_in[15];
    const float* o1b    = (const float*)d_in[16];
    const float* o2w    = (const float*)d_in[17];
    const float* o2b    = (const float*)d_in[18];
    float* out = (float*)d_out;

    const int NI_SMEM = (HID * HID + 8 * 512) * (int)sizeof(float);
    cudaFuncSetAttribute(edge_mma_kernel, cudaFuncAttributeMaxDynamicSharedMemorySize, EK_SMEM);
    cudaFuncSetAttribute(node_init,   cudaFuncAttributeMaxDynamicSharedMemorySize, NI_SMEM);
    cudaFuncSetAttribute(node_mma<0>, cudaFuncAttributeMaxDynamicSharedMemorySize, NM_SMEM);
    cudaFuncSetAttribute(node_mma<1>, cudaFuncAttributeMaxDynamicSharedMemorySize, NM_SMEM);

    edge_pre_kernel<<<(N_EDGES + 255) / 256, 256>>>(ei, pos, eattr, out);
    node_init<<<296, 256, NI_SMEM>>>(z, emb, cf1_w);

    for (int l = 0; l < 3; l++) {
        edge_mma_kernel<<<296, 256, EK_SMEM>>>(ei,
                                               mlp_w1 + (size_t)l * NF * HID, mlp_b1 + (size_t)l * HID,
                                               mlp_w2 + (size_t)l * HID * HID, mlp_b2 + (size_t)l * HID);
        if (l < 2) {
            node_mma<0><<<148, 512, NM_SMEM>>>(
                cf2_w + (size_t)l * HID * HID, cf2_b + (size_t)l * HID,
                lin_w + (size_t)l * HID * HID, lin_b + (size_t)l * HID,
                cf1_w + (size_t)(l + 1) * HID * HID,
                nullptr, nullptr, nullptr, batch, out);
        } else {
            node_mma<1><<<148, 512, NM_SMEM>>>(
                cf2_w + (size_t)l * HID * HID, cf2_b + (size_t)l * HID,
                lin_w + (size_t)l * HID * HID, lin_b + (size_t)l * HID,
                o1w, o1b, o2w, o2b, batch, out);
        }
    }
}

// round 17
// speedup vs baseline: 1.1804x; 1.0841x over previous
#include <cuda_runtime.h>
#include <cuda_fp16.h>
#include <cstdint>
#include <math.h>

#define N_NODES 20000
#define N_PAD   20096            // 157 * 128
#define NT_TILES 157
#define N_EDGES 640000
#define HID 128
#define NB 3
#define NGS 47
#define NF 50
#define B_GRAPHS 16
#define LOG2F_ 0.69314718055994530942f
#define CUTF 10.0f
#define PI_F 3.14159265358979323846f
#define EDGE_TILES (N_EDGES / 128)   // 5000

#define SA1 72
#define SA2 136

// ---- edge kernel smem byte offsets ----
#define OFF_W1h 0
#define OFF_W2h 18432
#define OFF_A   53248
#define OFF_H   71680
#define OFF_B1  106496
#define OFF_B2  107008
#define EK_SMEM 107520                    // 2 CTAs/SM

// ---- node kernel smem byte offsets (persistent, 1 CTA/SM) ----
#define NM_WA  0
#define NM_WB  34816
#define NM_WC  69632
#define NM_AT  104448
#define NM_HT  139264
#define NM_BA  174080
#define NM_BB  174592
#define NM_BO  175104
#define NM_O2  175360
#define NM_SMEM 175616

// ---------------- scratch ----------------
__device__ float g_h  [N_PAD * HID];
__device__ float g_xh [N_PAD * HID];
__device__ float g_agg[N_PAD * HID];
__device__ float g_Cc [N_EDGES];
__device__ half  g_feat[(size_t)N_EDGES * 64];

__device__ __forceinline__ float sspf(float x) {
    float e = __expf(-fabsf(x));
    return fmaxf(x, 0.f) + __logf(1.f + e) - LOG2F_;
}
__device__ __forceinline__ uint32_t smem_to_u32(const void* p) {
    uint32_t a;
    asm("{ .reg .u64 t; cvta.to.shared.u64 t, %1; cvt.u32.u64 %0, t; }" : "=r"(a) : "l"(p));
    return a;
}
__device__ __forceinline__ void ldm_x4(uint32_t& r0, uint32_t& r1, uint32_t& r2, uint32_t& r3, uint32_t a) {
    asm volatile("ldmatrix.sync.aligned.m8n8.x4.shared.b16 {%0,%1,%2,%3}, [%4];"
                 : "=r"(r0), "=r"(r1), "=r"(r2), "=r"(r3) : "r"(a));
}
__device__ __forceinline__ void ldm_x4t(uint32_t& r0, uint32_t& r1, uint32_t& r2, uint32_t& r3, uint32_t a) {
    asm volatile("ldmatrix.sync.aligned.m8n8.x4.trans.shared.b16 {%0,%1,%2,%3}, [%4];"
                 : "=r"(r0), "=r"(r1), "=r"(r2), "=r"(r3) : "r"(a));
}
__device__ __forceinline__ void mma16816(float* c, uint32_t a0, uint32_t a1, uint32_t a2, uint32_t a3,
                                         uint32_t b0, uint32_t b1) {
    asm volatile("mma.sync.aligned.m16n8k16.row.col.f32.f16.f16.f32 "
                 "{%0,%1,%2,%3}, {%4,%5,%6,%7}, {%8,%9}, {%0,%1,%2,%3};"
                 : "+f"(c[0]), "+f"(c[1]), "+f"(c[2]), "+f"(c[3])
                 : "r"(a0), "r"(a1), "r"(a2), "r"(a3), "r"(b0), "r"(b1));
}
__device__ __forceinline__ void cp_async16(uint32_t dst, const void* src) {
    asm volatile("cp.async.cg.shared.global [%0], [%1], 16;" :: "r"(dst), "l"(src) : "memory");
}
#define CP_COMMIT() asm volatile("cp.async.commit_group;" ::: "memory")
#define CP_WAIT0()  asm volatile("cp.async.wait_group 0;" ::: "memory")

__device__ __forceinline__ uint2 f4_to_h4(float4 v) {
    half2 h0 = __floats2half2_rn(v.x, v.y);
    half2 h1 = __floats2half2_rn(v.z, v.w);
    return make_uint2(*(uint32_t*)&h0, *(uint32_t*)&h1);
}

// ---------------- edge_pre (+ zero out) ----------------
__global__ void edge_pre_kernel(const int* __restrict__ ei, const float* __restrict__ pos,
                                const float* __restrict__ eattr, float* __restrict__ out) {
    cudaTriggerProgrammaticLaunchCompletion();
    int e = blockIdx.x * blockDim.x + threadIdx.x;
    if (blockIdx.x == 0 && threadIdx.x < B_GRAPHS) out[threadIdx.x] = 0.f;
    if (e >= N_EDGES) return;
    int r = ei[e], c = ei[N_EDGES + e];
    float dx = pos[r * 3 + 0] - pos[c * 3 + 0];
    float dy = pos[r * 3 + 1] - pos[c * 3 + 1];
    float dz = pos[r * 3 + 2] - pos[c * 3 + 2];
    float ew = sqrtf(dx * dx + dy * dy + dz * dz);
    g_Cc[e] = 0.5f * (cosf(ew * (PI_F / CUTF)) + 1.f);

    const float step = CUTF / (float)(NGS - 1);
    float fv[64];
    fv[0] = eattr[e * NB + 0];
    fv[1] = eattr[e * NB + 1];
    fv[2] = eattr[e * NB + 2];
    float u  = ew / step;
    float gs = __expf(-0.5f * u * u);
    float m  = __expf(u - 0.5f);
    const float d = 0.36787944117144233f;   // e^-1
    fv[3] = gs;
    #pragma unroll
    for (int k = 1; k < NGS; k++) {
        gs *= m;
        m  *= d;
        fv[3 + k] = gs;
    }
    #pragma unroll
    for (int k = NF; k < 64; k++) fv[k] = 0.f;

    half2 tmp[32];
    #pragma unroll
    for (int j = 0; j < 32; j++) tmp[j] = __floats2half2_rn(fv[2 * j], fv[2 * j + 1]);
    uint4* dst = (uint4*)(g_feat + (size_t)e * 64);
    #pragma unroll
    for (int j = 0; j < 8; j++) dst[j] = ((uint4*)tmp)[j];
}

// ---------------- node_init (independent of edge_pre; end-sync for transitivity) ----------------
__global__ void __launch_bounds__(256)
node_init(const int* __restrict__ z, const float* __restrict__ emb,
          const float* __restrict__ W) {
    cudaTriggerProgrammaticLaunchCompletion();
    extern __shared__ float sm[];
    float* Ws = sm;
    float* xs = Ws + HID * HID;
    for (int i = threadIdx.x; i < HID * HID; i += blockDim.x) Ws[i] = W[i];
    __syncthreads();

    const int wid = threadIdx.x >> 5, lane = threadIdx.x & 31;
    float* xw = xs + wid * 512;
    const int gw = blockIdx.x * 8 + wid, nw = gridDim.x * 8;
    const int c0 = lane * 4;

    for (int gidx = gw; gidx < N_PAD / 4; gidx += nw) {
        int n0 = gidx * 4;
        #pragma unroll
        for (int j = 0; j < 4; j++) {
            int nn = n0 + j;
            float4 v = make_float4(0.f, 0.f, 0.f, 0.f);
            if (nn < N_NODES) {
                int zr = z[nn];
                v = ((const float4*)(emb + (size_t)zr * HID))[lane];
            }
            ((float4*)xw)[lane + 32 * j] = v;
            ((float4*)(g_h + (size_t)nn * HID))[lane] = v;
            ((float4*)(g_agg + (size_t)nn * HID))[lane] = make_float4(0.f, 0.f, 0.f, 0.f);
        }
        __syncwarp();
        float a[4][4];
        #pragma unroll
        for (int r = 0; r < 4; r++) { a[r][0] = a[r][1] = a[r][2] = a[r][3] = 0.f; }
        #pragma unroll 4
        for (int k = 0; k < HID; k++) {
            float4 w = *(const float4*)(Ws + k * HID + c0);
            #pragma unroll
            for (int r = 0; r < 4; r++) {
                float v = xw[r * HID + k];
                a[r][0] += v * w.x; a[r][1] += v * w.y; a[r][2] += v * w.z; a[r][3] += v * w.w;
            }
        }
        #pragma unroll
        for (int r = 0; r < 4; r++)
            *(float4*)(g_xh + (size_t)(n0 + r) * HID + c0) =
                make_float4(a[r][0], a[r][1], a[r][2], a[r][3]);
        __syncwarp();
    }
    // ensure edge_pre (concurrent predecessor) completes before this kernel retires,
    // so edge_mma<0>'s dependency wait transitively covers it.
    cudaGridDependencySynchronize();
}

// ---------------- edge filter MLP ----------------
__global__ void __launch_bounds__(256, 2)
edge_mma_kernel(const int* __restrict__ ei,
                const float* __restrict__ w1, const float* __restrict__ b1,
                const float* __restrict__ w2, const float* __restrict__ b2) {
    cudaTriggerProgrammaticLaunchCompletion();
    extern __shared__ char smem[];
    half* w1h = (half*)(smem + OFF_W1h);
    half* w2h = (half*)(smem + OFF_W2h);
    half* Ah  = (half*)(smem + OFF_A);
    half* Hh  = (half*)(smem + OFF_H);
    float* b1s = (float*)(smem + OFF_B1);
    float* b2s = (float*)(smem + OFF_B2);

    const int tid = threadIdx.x, wid = tid >> 5, lane = tid & 31;
    const int g = lane >> 2, tg = lane & 3;
    const int rt = wid & 3, nh = wid >> 2;
    const int aedge = tid >> 1, aseg = tid & 1;

    // stage weights (params only — safe pre-dependency)
    for (int i = tid * 4; i < 64 * 128; i += 1024) {
        int k = i >> 7, n = i & 127;
        float4 v = (k < NF) ? *(const float4*)(w1 + k * HID + n)
                            : make_float4(0.f, 0.f, 0.f, 0.f);
        *(uint2*)(w1h + k * SA2 + n) = f4_to_h4(v);
    }
    for (int i = tid * 4; i < 128 * 128; i += 1024) {
        int k = i >> 7, n = i & 127;
        *(uint2*)(w2h + k * SA2 + n) = f4_to_h4(*(const float4*)(w2 + k * HID + n));
    }
    if (tid < HID) { b1s[tid] = b1[tid]; b2s[tid] = b2[tid]; }

    cudaGridDependencySynchronize();   // predecessor outputs (g_feat/g_agg/g_xh/g_Cc) now valid

    const uint32_t aU  = smem_to_u32(Ah);
    const uint32_t hU  = smem_to_u32(Hh);
    const uint32_t w1U = smem_to_u32(w1h);
    const uint32_t w2U = smem_to_u32(w2h);
    const int lrow = lane & 15;
    const int lkh  = (lane >> 4) << 3;

    const uint32_t aCp = aU + (uint32_t)((aedge * SA1 + aseg * 32) << 1);
    {
        const half* src = g_feat + ((size_t)blockIdx.x * 128 + aedge) * 64 + aseg * 32;
        #pragma unroll
        for (int j = 0; j < 4; j++) cp_async16(aCp + j * 16, src + j * 8);
        CP_COMMIT();
    }
    CP_WAIT0();
    __syncthreads();

    for (int t = blockIdx.x; t < EDGE_TILES; t += gridDim.x) {
        const int e0 = t * 128;
        float acc[2][8][4];
        #pragma unroll
        for (int mt = 0; mt < 2; mt++)
            #pragma unroll
            for (int j = 0; j < 8; j++)
                #pragma unroll
                for (int q = 0; q < 4; q++) acc[mt][j][q] = 0.f;

        // ---- GEMM1 ----
        #pragma unroll
        for (int ks = 0; ks < 4; ks++) {
            const int k0 = ks * 16;
            uint32_t am[2][4];
            #pragma unroll
            for (int mt = 0; mt < 2; mt++) {
                uint32_t addr = aU + (uint32_t)(((rt * 32 + mt * 16 + lrow) * SA1 + k0 + lkh) << 1);
                ldm_x4(am[mt][0], am[mt][1], am[mt][2], am[mt][3], addr);
            }
            #pragma unroll
            for (int jj = 0; jj < 4; jj++) {
                uint32_t r0, r1, r2, r3;
                uint32_t addr = w1U + (uint32_t)(((k0 + lrow) * SA2 + nh * 64 + jj * 16 + lkh) << 1);
                ldm_x4t(r0, r1, r2, r3, addr);
                #pragma unroll
                for (int mt = 0; mt < 2; mt++) {
                    mma16816(acc[mt][2 * jj],     am[mt][0], am[mt][1], am[mt][2], am[mt][3], r0, r1);
                    mma16816(acc[mt][2 * jj + 1], am[mt][0], am[mt][1], am[mt][2], am[mt][3], r2, r3);
                }
            }
        }
        __syncthreads();

        const int tn = t + gridDim.x;
        if (tn < EDGE_TILES) {
            const half* src = g_feat + ((size_t)tn * 128 + aedge) * 64 + aseg * 32;
            #pragma unroll
            for (int j = 0; j < 4; j++) cp_async16(aCp + j * 16, src + j * 8);
        }
        CP_COMMIT();

        // ---- epilogue1: H = fp16(ssp(D1 + b1)) ----
        #pragma unroll
        for (int mt = 0; mt < 2; mt++) {
            int r0 = rt * 32 + mt * 16 + g;
            #pragma unroll
            for (int j = 0; j < 8; j++) {
                int c = nh * 64 + j * 8 + tg * 2;
                float bx = b1s[c], by = b1s[c + 1];
                *(half2*)(Hh + (size_t)r0 * SA2 + c) =
                    __floats2half2_rn(sspf(acc[mt][j][0] + bx), sspf(acc[mt][j][1] + by));
                *(half2*)(Hh + (size_t)(r0 + 8) * SA2 + c) =
                    __floats2half2_rn(sspf(acc[mt][j][2] + bx), sspf(acc[mt][j][3] + by));
            }
        }
        __syncthreads();

        // ---- GEMM2 ----
        #pragma unroll
        for (int mt = 0; mt < 2; mt++)
            #pragma unroll
            for (int j = 0; j < 8; j++)
                #pragma unroll
                for (int q = 0; q < 4; q++) acc[mt][j][q] = 0.f;
        #pragma unroll
        for (int ks = 0; ks < 8; ks++) {
            const int k0 = ks * 16;
            uint32_t am[2][4];
            #pragma unroll
            for (int mt = 0; mt < 2; mt++) {
                uint32_t addr = hU + (uint32_t)(((rt * 32 + mt * 16 + lrow) * SA2 + k0 + lkh) << 1);
                ldm_x4(am[mt][0], am[mt][1], am[mt][2], am[mt][3], addr);
            }
            #pragma unroll
            for (int jj = 0; jj < 4; jj++) {
                uint32_t r0, r1, r2, r3;
                uint32_t addr = w2U + (uint32_t)(((k0 + lrow) * SA2 + nh * 64 + jj * 16 + lkh) << 1);
                ldm_x4t(r0, r1, r2, r3, addr);
                #pragma unroll
                for (int mt = 0; mt < 2; mt++) {
                    mma16816(acc[mt][2 * jj],     am[mt][0], am[mt][1], am[mt][2], am[mt][3], r0, r1);
                    mma16816(acc[mt][2 * jj + 1], am[mt][0], am[mt][1], am[mt][2], am[mt][3], r2, r3);
                }
            }
        }
        __syncthreads();

        // ---- epilogue2: single-pass fp16 staging; meta loads overlap staging ----
        int rowi[8], coli[8];
        float Ci[8];
        #pragma unroll
        for (int q = 0; q < 8; q++) {
            int cr = wid * 16 + q;
            int mt = cr >> 6, cr64 = cr & 63;
            int er = (cr64 >> 4) * 32 + mt * 16 + (cr64 & 15);
            int e = e0 + er;
            rowi[q] = ei[e];
            coli[q] = ei[N_EDGES + e];
            Ci[q]   = g_Cc[e];
        }
        #pragma unroll
        for (int mt = 0; mt < 2; mt++) {
            int cr0 = mt * 64 + rt * 16 + g;
            #pragma unroll
            for (int j = 0; j < 8; j++) {
                int c = nh * 64 + j * 8 + tg * 2;
                float bx = b2s[c], by = b2s[c + 1];
                *(half2*)(Hh + (size_t)cr0 * SA2 + c) =
                    __floats2half2_rn(acc[mt][j][0] + bx, acc[mt][j][1] + by);
                *(half2*)(Hh + (size_t)(cr0 + 8) * SA2 + c) =
                    __floats2half2_rn(acc[mt][j][2] + bx, acc[mt][j][3] + by);
            }
        }
        __syncthreads();
        #pragma unroll
        for (int hb = 0; hb < 2; hb++) {
            #pragma unroll
            for (int q = 0; q < 8; q++) {
                int cr = wid * 16 + hb * 8 + q;
                float4 xv = *(const float4*)(g_xh + (size_t)rowi[q] * HID + lane * 4);
                uint2 wraw = *(const uint2*)(Hh + (size_t)cr * SA2 + lane * 4);
                float2 f01 = __half22float2(*(half2*)&wraw.x);
                float2 f23 = __half22float2(*(half2*)&wraw.y);
                float C = Ci[q];
                float m0 = f01.x * C * xv.x;
                float m1 = f01.y * C * xv.y;
                float m2 = f23.x * C * xv.z;
                float m3 = f23.y * C * xv.w;
                asm volatile("red.global.add.v4.f32 [%0], {%1, %2, %3, %4};"
                             :: "l"(g_agg + (size_t)coli[q] * HID + lane * 4),
                                "f"(m0), "f"(m1), "f"(m2), "f"(m3) : "memory");
            }
            if (hb == 0) {
                #pragma unroll
                for (int q = 0; q < 8; q++) {
                    int cr = wid * 16 + 8 + q;
                    int mt = cr >> 6, cr64 = cr & 63;
                    int er = (cr64 >> 4) * 32 + mt * 16 + (cr64 & 15);
                    int e = e0 + er;
                    rowi[q] = ei[e];
                    coli[q] = ei[N_EDGES + e];
                    Ci[q]   = g_Cc[e];
                }
            }
        }
        CP_WAIT0();
        __syncthreads();
    }
}

// ---------------- node phase (persistent, 512 threads, M=128 tiles) ----------------
template <int LAST>
__global__ void __launch_bounds__(512, 1)
node_mma(const float* __restrict__ wA, const float* __restrict__ bA,
         const float* __restrict__ wB, const float* __restrict__ bB,
         const float* __restrict__ wC,
         const float* __restrict__ o1b, const float* __restrict__ o2w,
         const float* __restrict__ o2b,
         const int* __restrict__ batch, float* __restrict__ out) {
    cudaTriggerProgrammaticLaunchCompletion();
    extern __shared__ char smem[];
    half* WAh = (half*)(smem + NM_WA);
    half* WBh = (half*)(smem + NM_WB);
    half* WCh = (half*)(smem + NM_WC);
    half* Ah  = (half*)(smem + NM_AT);
    half* Hh  = (half*)(smem + NM_HT);
    float* bAs = (float*)(smem + NM_BA);
    float* bBs = (float*)(smem + NM_BB);
    float* BOs = (float*)(smem + NM_BO);
    float* O2s = (float*)(smem + NM_O2);

    const int tid = threadIdx.x, wid = tid >> 5, lane = tid & 31;
    const int g = lane >> 2, tg = lane & 3;
    const int rt = wid & 7, nh = wid >> 3;

    // weight staging (params only — safe pre-dependency)
    for (int i = tid * 4; i < 128 * 128; i += 2048) {
        int k = i >> 7, n = i & 127;
        *(uint2*)(WAh + k * SA2 + n) = f4_to_h4(*(const float4*)(wA + k * HID + n));
        *(uint2*)(WBh + k * SA2 + n) = f4_to_h4(*(const float4*)(wB + k * HID + n));
    }
    if (LAST) {
        for (int i = tid * 4; i < 128 * 64; i += 2048) {
            int k = i >> 6, n = i & 63;
            *(uint2*)(WCh + k * SA2 + n) = f4_to_h4(*(const float4*)(wC + k * 64 + n));
        }
        if (tid < 64) { BOs[tid] = o1b[tid]; O2s[tid] = o2w[tid]; }
    } else {
        for (int i = tid * 4; i < 128 * 128; i += 2048) {
            int k = i >> 7, n = i & 127;
            *(uint2*)(WCh + k * SA2 + n) = f4_to_h4(*(const float4*)(wC + k * HID + n));
        }
    }
    if (tid < HID) { bAs[tid] = bA[tid]; bBs[tid] = bB[tid]; }

    cudaGridDependencySynchronize();   // edge_mma outputs (g_agg) now valid

    const uint32_t aU  = smem_to_u32(Ah);
    const uint32_t hU  = smem_to_u32(Hh);
    const uint32_t wAU = smem_to_u32(WAh);
    const uint32_t wBU = smem_to_u32(WBh);
    const uint32_t wCU = smem_to_u32(WCh);
    const int lrow = lane & 15;
    const int lkh  = (lane >> 4) << 3;
    const float ob = LAST ? o2b[0] : 0.f;

    for (int t = blockIdx.x; t < NT_TILES; t += gridDim.x) {
        const int n0 = t * 128;
        {
            float4 pv[8];
            #pragma unroll
            for (int j = 0; j < 8; j++) {
                int i = tid + j * 512;
                pv[j] = ((const float4*)(g_agg + (size_t)(n0 + (i >> 5)) * HID))[i & 31];
            }
            #pragma unroll
            for (int j = 0; j < 8; j++) {
                int i = tid + j * 512;
                ((float4*)(g_agg + (size_t)(n0 + (i >> 5)) * HID))[i & 31] =
                    make_float4(0.f, 0.f, 0.f, 0.f);
                *(uint2*)(Ah + (size_t)(i >> 5) * SA2 + (i & 31) * 4) = f4_to_h4(pv[j]);
            }
        }
        __syncthreads();

        float acc[8][4];
        // ---- GEMM1: A @ WA ----
        #pragma unroll
        for (int j = 0; j < 8; j++)
            #pragma unroll
            for (int q = 0; q < 4; q++) acc[j][q] = 0.f;
        #pragma unroll
        for (int ks = 0; ks < 8; ks++) {
            const int k0 = ks * 16;
            uint32_t am[4];
            uint32_t addr = aU + (uint32_t)(((rt * 16 + lrow) * SA2 + k0 + lkh) << 1);
            ldm_x4(am[0], am[1], am[2], am[3], addr);
            #pragma unroll
            for (int jj = 0; jj < 4; jj++) {
                uint32_t r0, r1, r2, r3;
                uint32_t baddr = wAU + (uint32_t)(((k0 + lrow) * SA2 + nh * 64 + jj * 16 + lkh) << 1);
                ldm_x4t(r0, r1, r2, r3, baddr);
                mma16816(acc[2 * jj],     am[0], am[1], am[2], am[3], r0, r1);
                mma16816(acc[2 * jj + 1], am[0], am[1], am[2], am[3], r2, r3);
            }
        }
        {
            int r0 = rt * 16 + g;
            #pragma unroll
            for (int j = 0; j < 8; j++) {
                int c = nh * 64 + j * 8 + tg * 2;
                float bx = bAs[c], by = bAs[c + 1];
                *(half2*)(Hh + (size_t)r0 * SA2 + c) =
                    __floats2half2_rn(sspf(acc[j][0] + bx), sspf(acc[j][1] + by));
                *(half2*)(Hh + (size_t)(r0 + 8) * SA2 + c) =
                    __floats2half2_rn(sspf(acc[j][2] + bx), sspf(acc[j][3] + by));
            }
        }
        __syncthreads();

        // ---- GEMM2: H @ WB ----
        #pragma unroll
        for (int j = 0; j < 8; j++)
            #pragma unroll
            for (int q = 0; q < 4; q++) acc[j][q] = 0.f;
        #pragma unroll
        for (int ks = 0; ks < 8; ks++) {
            const int k0 = ks * 16;
            uint32_t am[4];
            uint32_t addr = hU + (uint32_t)(((rt * 16 + lrow) * SA2 + k0 + lkh) << 1);
            ldm_x4(am[0], am[1], am[2], am[3], addr);
            #pragma unroll
            for (int jj = 0; jj < 4; jj++) {
                uint32_t r0, r1, r2, r3;
                uint32_t baddr = wBU + (uint32_t)(((k0 + lrow) * SA2 + nh * 64 + jj * 16 + lkh) << 1);
                ldm_x4t(r0, r1, r2, r3, baddr);
                mma16816(acc[2 * jj],     am[0], am[1], am[2], am[3], r0, r1);
                mma16816(acc[2 * jj + 1], am[0], am[1], am[2], am[3], r2, r3);
            }
        }
        {
            int r0 = rt * 16 + g;
            int gr0 = n0 + r0;
            #pragma unroll
            for (int j = 0; j < 8; j++) {
                int c = nh * 64 + j * 8 + tg * 2;
                float bx = bBs[c], by = bBs[c + 1];
                float2 h0 = *(const float2*)(g_h + (size_t)gr0 * HID + c);
                float2 h1 = *(const float2*)(g_h + (size_t)(gr0 + 8) * HID + c);
                float n00 = acc[j][0] + bx + h0.x;
                float n01 = acc[j][1] + by + h0.y;
                float n10 = acc[j][2] + bx + h1.x;
                float n11 = acc[j][3] + by + h1.y;
                if (!LAST) {
                    *(float2*)(g_h + (size_t)gr0 * HID + c)       = make_float2(n00, n01);
                    *(float2*)(g_h + (size_t)(gr0 + 8) * HID + c) = make_float2(n10, n11);
                }
                *(half2*)(Ah + (size_t)r0 * SA2 + c)       = __floats2half2_rn(n00, n01);
                *(half2*)(Ah + (size_t)(r0 + 8) * SA2 + c) = __floats2half2_rn(n10, n11);
            }
        }
        __syncthreads();

        // ---- GEMM3: A' @ WC ----
        const int NJ3 = LAST ? 2 : 4;
        #pragma unroll
        for (int j = 0; j < 8; j++)
            #pragma unroll
            for (int q = 0; q < 4; q++) acc[j][q] = 0.f;
        #pragma unroll
        for (int ks = 0; ks < 8; ks++) {
            const int k0 = ks * 16;
            uint32_t am[4];
            uint32_t addr = aU + (uint32_t)(((rt * 16 + lrow) * SA2 + k0 + lkh) << 1);
            ldm_x4(am[0], am[1], am[2], am[3], addr);
            #pragma unroll
            for (int jj = 0; jj < 4; jj++) {
                if (jj >= NJ3) break;
                uint32_t r0, r1, r2, r3;
                int ncol = LAST ? (nh * 32 + jj * 16) : (nh * 64 + jj * 16);
                uint32_t baddr = wCU + (uint32_t)(((k0 + lrow) * SA2 + ncol + lkh) << 1);
                ldm_x4t(r0, r1, r2, r3, baddr);
                mma16816(acc[2 * jj],     am[0], am[1], am[2], am[3], r0, r1);
                mma16816(acc[2 * jj + 1], am[0], am[1], am[2], am[3], r2, r3);
            }
        }
        if (!LAST) {
            int gr0 = n0 + rt * 16 + g;
            #pragma unroll
            for (int j = 0; j < 8; j++) {
                int c = nh * 64 + j * 8 + tg * 2;
                *(float2*)(g_xh + (size_t)gr0 * HID + c) =
                    make_float2(acc[j][0], acc[j][1]);
                *(float2*)(g_xh + (size_t)(gr0 + 8) * HID + c) =
                    make_float2(acc[j][2], acc[j][3]);
            }
        } else {
            float s0 = 0.f, s1 = 0.f;
            #pragma unroll
            for (int j = 0; j < 4; j++) {
                int c = nh * 32 + j * 8 + tg * 2;
                float bx = BOs[c], by = BOs[c + 1];
                float wx = O2s[c], wy = O2s[c + 1];
                s0 += sspf(acc[j][0] + bx) * wx + sspf(acc[j][1] + by) * wy;
                s1 += sspf(acc[j][2] + bx) * wx + sspf(acc[j][3] + by) * wy;
            }
            s0 += __shfl_xor_sync(0xffffffffu, s0, 1);
            s0 += __shfl_xor_sync(0xffffffffu, s0, 2);
            s1 += __shfl_xor_sync(0xffffffffu, s1, 1);
            s1 += __shfl_xor_sync(0xffffffffu, s1, 2);
            if (tg == 0) {
                int rowA = n0 + rt * 16 + g;
                int rowB = rowA + 8;
                float add = (nh == 0) ? ob : 0.f;
                if (rowA < N_NODES) atomicAdd(&out[batch[rowA]], s0 + add);
                if (rowB < N_NODES) atomicAdd(&out[batch[rowB]], s1 + add);
            }
        }
        __syncthreads();
    }
}

// ---------------- launch (PDL chain) ----------------
extern "C" void kernel_launch(void* const* d_in, const int* in_sizes, int n_in,
                              void* d_out, int out_size) {
    const int*   z      = (const int*)  d_in[0];
    const float* pos    = (const float*)d_in[1];
    const int*   batch  = (const int*)  d_in[2];
    const int*   ei     = (const int*)  d_in[3];
    const float* eattr  = (const float*)d_in[4];
    const float* emb    = (const float*)d_in[5];
    const float* mlp_w1 = (const float*)d_in[6];
    const float* mlp_b1 = (const float*)d_in[7];
    const float* mlp_w2 = (const float*)d_in[8];
    const float* mlp_b2 = (const float*)d_in[9];
    const float* cf1_w  = (const float*)d_in[10];
    const float* cf2_w  = (const float*)d_in[11];
    const float* cf2_b  = (const float*)d_in[12];
    const float* lin_w  = (const float*)d_in[13];
    const float* lin_b  = (const float*)d_in[14];
    const float* o1w    = (const float*)d_in[15];
    const float* o1b    = (const float*)d_in[16];
    const float* o2w    = (const float*)d_in[17];
    const float* o2b    = (const float*)d_in[18];
    float* out = (float*)d_out;

    const int NI_SMEM = (HID * HID + 8 * 512) * (int)sizeof(float);
    cudaFuncSetAttribute(edge_mma_kernel, cudaFuncAttributeMaxDynamicSharedMemorySize, EK_SMEM);
    cudaFuncSetAttribute(node_init,   cudaFuncAttributeMaxDynamicSharedMemorySize, NI_SMEM);
    cudaFuncSetAttribute(node_mma<0>, cudaFuncAttributeMaxDynamicSharedMemorySize, NM_SMEM);
    cudaFuncSetAttribute(node_mma<1>, cudaFuncAttributeMaxDynamicSharedMemorySize, NM_SMEM);

    cudaLaunchAttribute pdl[1];
    pdl[0].id = cudaLaunchAttributeProgrammaticStreamSerialization;
    pdl[0].val.programmaticStreamSerializationAllowed = 1;

    // edge_pre: normal launch
    edge_pre_kernel<<<(N_EDGES + 255) / 256, 256>>>(ei, pos, eattr, out);

    // node_init: PDL (overlaps edge_pre; end-sync keeps ordering for edge_mma<0>)
    {
        cudaLaunchConfig_t cfg = {};
        cfg.gridDim = dim3(296); cfg.blockDim = dim3(256);
        cfg.dynamicSmemBytes = NI_SMEM;
        cfg.attrs = pdl; cfg.numAttrs = 1;
        cudaLaunchKernelEx(&cfg, node_init, z, emb, cf1_w);
    }

    for (int l = 0; l < 3; l++) {
        {
            cudaLaunchConfig_t cfg = {};
            cfg.gridDim = dim3(296); cfg.blockDim = dim3(256);
            cfg.dynamicSmemBytes = EK_SMEM;
            cfg.attrs = pdl; cfg.numAttrs = 1;
            cudaLaunchKernelEx(&cfg, edge_mma_kernel, ei,
                               (const float*)(mlp_w1 + (size_t)l * NF * HID),
                               (const float*)(mlp_b1 + (size_t)l * HID),
                               (const float*)(mlp_w2 + (size_t)l * HID * HID),
                               (const float*)(mlp_b2 + (size_t)l * HID));
        }
        cudaLaunchConfig_t cfg = {};
        cfg.gridDim = dim3(148); cfg.blockDim = dim3(512);
        cfg.dynamicSmemBytes = NM_SMEM;
        cfg.attrs = pdl; cfg.numAttrs = 1;
        if (l < 2) {
            cudaLaunchKernelEx(&cfg, node_mma<0>,
                               (const float*)(cf2_w + (size_t)l * HID * HID),
                               (const float*)(cf2_b + (size_t)l * HID),
                               (const float*)(lin_w + (size_t)l * HID * HID),
                               (const float*)(lin_b + (size_t)l * HID),
                               (const float*)(cf1_w + (size_t)(l + 1) * HID * HID),
                               (const float*)nullptr, (const float*)nullptr,
                               (const float*)nullptr, batch, out);
        } else {
            cudaLaunchKernelEx(&cfg, node_mma<1>,
                               (const float*)(cf2_w + (size_t)l * HID * HID),
                               (const float*)(cf2_b + (size_t)l * HID),
                               (const float*)(lin_w + (size_t)l * HID * HID),
                               (const float*)(lin_b + (size_t)l * HID),
                               o1w, o1b, o2w, o2b, batch, out);
        }
    }
}